// round 12
// baseline (speedup 1.0000x reference)
#include <cuda_runtime.h>
#include <cstdint>

#define NN   51200
#define NE   819200
#define NG   256
#define NN2  102400
#define NA   204800
#define NE2  409600
#define ND   64
#define NL   5
#define NNI2 36
#define NNAF 40
#define FEPS 1e-5f

typedef unsigned long long u64;

// ---------------- side streams for graph-level concurrency ----------------
struct HXStreams {
    cudaStream_t sB, sC;
    cudaEvent_t evRoot, evB, evC, evRoot2, evB2;
    HXStreams() {
        cudaStreamCreateWithFlags(&sB, cudaStreamNonBlocking);
        cudaStreamCreateWithFlags(&sC, cudaStreamNonBlocking);
        cudaEventCreateWithFlags(&evRoot,  cudaEventDisableTiming);
        cudaEventCreateWithFlags(&evB,     cudaEventDisableTiming);
        cudaEventCreateWithFlags(&evC,     cudaEventDisableTiming);
        cudaEventCreateWithFlags(&evRoot2, cudaEventDisableTiming);
        cudaEventCreateWithFlags(&evB2,    cudaEventDisableTiming);
    }
};
static HXStreams g_hx;

// PDL launch helper: dependent kernel may start its prologue while the
// predecessor drains; the kernel calls cudaGridDependencySynchronize()
// before touching predecessor-produced data.
template <typename... KA, typename... AA>
static inline void pdl_launch(void (*kern)(KA...), dim3 g, dim3 b, AA... args) {
    cudaLaunchConfig_t cfg = {};
    cfg.gridDim = g; cfg.blockDim = b; cfg.dynamicSmemBytes = 0; cfg.stream = 0;
    cudaLaunchAttribute at;
    at.id = cudaLaunchAttributeProgrammaticStreamSerialization;
    at.val.programmaticStreamSerializationAllowed = 1;
    cfg.attrs = &at; cfg.numAttrs = 1;
    cudaLaunchKernelEx(&cfg, kern, static_cast<KA>(args)...);
}

// ---------------- f32x2 packed helpers ----------------
__device__ __forceinline__ u64 pk2(float x, float y) {
    u64 r; asm("mov.b64 %0, {%1,%2};" : "=l"(r) : "f"(x), "f"(y)); return r;
}
__device__ __forceinline__ float2 up2(u64 v) {
    float2 r; asm("mov.b64 {%0,%1}, %2;" : "=f"(r.x), "=f"(r.y) : "l"(v)); return r;
}
__device__ __forceinline__ u64 f2fma(float a, u64 b, u64 c) {
    u64 d;
    asm("{\n\t.reg .b64 ra;\n\tmov.b64 ra, {%1,%1};\n\tfma.rn.f32x2 %0, ra, %2, %3;\n\t}"
        : "=l"(d) : "f"(a), "l"(b), "l"(c));
    return d;
}
__device__ __forceinline__ u64 add2(u64 a, u64 b) {
    u64 d; asm("add.rn.f32x2 %0, %1, %2;" : "=l"(d) : "l"(a), "l"(b)); return d;
}

// ---------------- device scratch ----------------
__device__ float g_h[NN * ND];      // embed output (layer-0 input)
__device__ float g_agg[NN * ND];
__device__ float g_h2[NN * ND];     // raw MLP output per layer (pre-BN)

__device__ int g_cnt12[NN * 12];
__device__ int g_deg1[NN];
__device__ int g_base1[NN];
__device__ int g_cursor1[NN];
__device__ int g_adj1[NE];
__device__ int g_total1;

__device__ int g_deg2[NN2];
__device__ int g_base2[NN2];
__device__ int g_cursor2[NN2];
__device__ int g_adj2[NE2];
__device__ int g_total2;

__device__ float g_xpf[NN2 * ND];
__device__ int   g_iso[NN2];
__device__ float g_zr[NN2 * ND];
__device__ float g_zroot[NN2 * ND];

__device__ float g_bnsumL[NL * ND];
__device__ float g_bnsqL[NL * ND];

__device__ float g_x1[NG * ND];
__device__ float g_x2[NG * ND];

// ---------------- zero ----------------
__global__ void k_zero1() {
    int i = blockIdx.x * blockDim.x + threadIdx.x;
    int stride = gridDim.x * blockDim.x;
    for (int j = i; j < NN * 12; j += stride) g_cnt12[j] = 0;
    for (int j = i; j < NL * ND; j += stride) { g_bnsumL[j] = 0.f; g_bnsqL[j] = 0.f; }
    if (i == 0) g_total1 = 0;
}
__global__ void k_zero2() {
    int i = blockIdx.x * blockDim.x + threadIdx.x;
    int stride = gridDim.x * blockDim.x;
    for (int j = i; j < NN2; j += stride) g_deg2[j] = 0;
    if (i == 0) g_total2 = 0;
}

// ---------------- counts ----------------
__global__ void k_count1(const int* __restrict__ ei, const int* __restrict__ ea) {
    int e = blockIdx.x * blockDim.x + threadIdx.x;
    if (e >= NE) return;
    int dst = ei[NE + e];
    int2 aa = __ldg((const int2*)(ea) + e);
    atomicAdd(&g_cnt12[dst * 12 + aa.x * 3 + aa.y], 1);
}
__global__ void k_count2(const int* __restrict__ ei2) {
    int e = blockIdx.x * blockDim.x + threadIdx.x;
    if (e >= NE2) return;
    atomicAdd(&g_deg2[ei2[NE2 + e]], 1);
}

// ---------------- reserve CSR ranges ----------------
__global__ void k_reserve1() {
    int i = blockIdx.x * blockDim.x + threadIdx.x;
    int lane = threadIdx.x & 31;
    if (i >= NN) return;
    int d = 0;
    #pragma unroll
    for (int c = 0; c < 12; c++) d += g_cnt12[i * 12 + c];
    g_deg1[i] = d;
    int incl = d;
    #pragma unroll
    for (int o = 1; o < 32; o <<= 1) {
        int t = __shfl_up_sync(0xffffffffu, incl, o);
        if (lane >= o) incl += t;
    }
    int tot = __shfl_sync(0xffffffffu, incl, 31);
    int base = 0;
    if (lane == 0) base = atomicAdd(&g_total1, tot);
    base = __shfl_sync(0xffffffffu, base, 0);
    int start = base + incl - d;
    g_base1[i] = start; g_cursor1[i] = start;
}
__global__ void k_reserve2() {
    int i = blockIdx.x * blockDim.x + threadIdx.x;
    int lane = threadIdx.x & 31;
    if (i >= NN2) return;
    int d = g_deg2[i];
    int incl = d;
    #pragma unroll
    for (int o = 1; o < 32; o <<= 1) {
        int t = __shfl_up_sync(0xffffffffu, incl, o);
        if (lane >= o) incl += t;
    }
    int tot = __shfl_sync(0xffffffffu, incl, 31);
    int base = 0;
    if (lane == 0) base = atomicAdd(&g_total2, tot);
    base = __shfl_sync(0xffffffffu, base, 0);
    int start = base + incl - d;
    g_base2[i] = start; g_cursor2[i] = start;
}

// ---------------- CSR fill ----------------
__global__ void k_fill1(const int* __restrict__ ei) {
    int e = blockIdx.x * blockDim.x + threadIdx.x;
    if (e >= NE) return;
    int dst = ei[NE + e];
    int pos = atomicAdd(&g_cursor1[dst], 1);
    g_adj1[pos] = ei[e];
}
__global__ void k_fill2(const int* __restrict__ ei2) {
    int e = blockIdx.x * blockDim.x + threadIdx.x;
    if (e >= NE2) return;
    int dst = ei2[NE2 + e];
    int pos = atomicAdd(&g_cursor2[dst], 1);
    g_adj2[pos] = ei2[e];
}

// ---------------- embed: h = relu(x @ embW + embB) ----------------
__global__ __launch_bounds__(128) void k_embed(const float* __restrict__ x,
                                               const float* __restrict__ W,
                                               const float* __restrict__ b) {
    __shared__ float Ws[NNAF * ND];
    __shared__ float bs[ND];
    __shared__ float row[2][NNAF];
    int tid = threadIdx.x;
    for (int i = tid; i < NNAF * ND; i += 128) Ws[i] = W[i];
    if (tid < 64) bs[tid] = b[tid];
    __syncthreads();
    int slot = tid >> 6, c = tid & 63;
    for (int base = blockIdx.x * 2; base < NN; base += gridDim.x * 2) {
        if (tid < 2 * NNAF) row[tid / NNAF][tid % NNAF] = x[(size_t)base * NNAF + tid];
        __syncthreads();
        float acc = bs[c];
        #pragma unroll
        for (int k = 0; k < NNAF; k++) acc = fmaf(row[slot][k], Ws[k * 64 + c], acc);
        g_h[(size_t)(base + slot) * 64 + c] = fmaxf(acc, 0.f);
        __syncthreads();
    }
}

// ---------------- GIN aggregation with fused BN+ReLU of the previous layer ----------------
__global__ __launch_bounds__(256) void k_agg1(const float* __restrict__ e1,
                                              const float* __restrict__ e2,
                                              const float* __restrict__ gammaP,
                                              const float* __restrict__ betaP,
                                              int layer) {
    const float* hsrc = (layer == 0) ? g_h : g_h2;
    __shared__ float comb[12][64];
    __shared__ float selfe[64];
    __shared__ float scs[64], shs[64];
    int tid = threadIdx.x;
    // prologue: edge-embedding tables from inputs (safe pre-sync)
    for (int idx = tid; idx < 12 * 64; idx += 256) {
        int cc = idx >> 6, d = idx & 63;
        comb[cc][d] = e1[(cc / 3) * 64 + d] + e2[(cc % 3) * 64 + d];
    }
    if (tid < 64) selfe[tid] = e1[4 * 64 + tid] + e2[0 * 64 + tid];
    cudaGridDependencySynchronize();
    if (tid < 64) {
        if (layer == 0) {
            scs[tid] = 1.f; shs[tid] = 0.f;
        } else {
            int pl = layer - 1;
            float mu = g_bnsumL[pl * 64 + tid] * (1.f / (float)NN);
            float var = g_bnsqL[pl * 64 + tid] * (1.f / (float)NN) - mu * mu;
            float s = gammaP[tid] * rsqrtf(var + FEPS);
            scs[tid] = s;
            shs[tid] = betaP[tid] - mu * s;
        }
    }
    __syncthreads();

    int warp = (blockIdx.x * 256 + tid) >> 5;
    if (warp >= NN) return;
    int n = warp;
    int lane = tid & 31;
    float scx = scs[2 * lane], scy = scs[2 * lane + 1];
    float shx = shs[2 * lane], shy = shs[2 * lane + 1];

    int cnt = (lane < 12) ? __ldg(&g_cnt12[n * 12 + lane]) : 0;

    float2 hv = __ldg((const float2*)(hsrc + ((size_t)n << 6) + (lane << 1)));
    float2 se = ((const float2*)selfe)[lane];
    float ax0 = fmaxf(fmaf(scx, hv.x, shx), 0.f) + se.x;
    float ay0 = fmaxf(fmaf(scy, hv.y, shy), 0.f) + se.y;
    float ax1 = 0.f, ay1 = 0.f;

    #pragma unroll
    for (int c = 0; c < 12; c++) {
        float cc = (float)__shfl_sync(0xffffffffu, cnt, c);
        float2 w = ((const float2*)comb[c])[lane];
        if (c & 1) { ax1 = fmaf(cc, w.x, ax1); ay1 = fmaf(cc, w.y, ay1); }
        else       { ax0 = fmaf(cc, w.x, ax0); ay0 = fmaf(cc, w.y, ay0); }
    }

    int beg = __ldg(&g_base1[n]);
    int end = beg + __ldg(&g_deg1[n]);
    int j = beg;
    for (; j + 32 <= end; j += 32) {
        int s = __ldg(&g_adj1[j + lane]);
        #pragma unroll
        for (int t = 0; t < 32; t++) {
            int src = __shfl_sync(0xffffffffu, s, t);
            float2 v = __ldg((const float2*)(hsrc + ((size_t)src << 6) + (lane << 1)));
            float vx = fmaxf(fmaf(scx, v.x, shx), 0.f);
            float vy = fmaxf(fmaf(scy, v.y, shy), 0.f);
            if (t & 1) { ax1 += vx; ay1 += vy; }
            else       { ax0 += vx; ay0 += vy; }
        }
    }
    if (j < end) {
        int idx = j + lane;
        int s = (idx < end) ? __ldg(&g_adj1[idx]) : 0;
        int c = end - j;
        for (int t = 0; t < c; t++) {
            int src = __shfl_sync(0xffffffffu, s, t);
            float2 v = __ldg((const float2*)(hsrc + ((size_t)src << 6) + (lane << 1)));
            float vx = fmaxf(fmaf(scx, v.x, shx), 0.f);
            float vy = fmaxf(fmaf(scy, v.y, shy), 0.f);
            if (t & 1) { ax1 += vx; ay1 += vy; }
            else       { ax0 += vx; ay0 += vy; }
        }
    }
    float2 o; o.x = ax0 + ax1; o.y = ay0 + ay1;
    *(float2*)(g_agg + ((size_t)n << 6) + (lane << 1)) = o;
}

// ---------------- GIN MLP v3: 4-row batch, K-split, ILP-4 ----------------
__global__ __launch_bounds__(256) void k_mlp(const float* __restrict__ W1,
                                             const float* __restrict__ b1,
                                             const float* __restrict__ W2,
                                             const float* __restrict__ b2,
                                             int layer) {
    __shared__ __align__(16) float rowf[4][64];
    __shared__ __align__(16) float midf[4][128];
    __shared__ u64 part[1024];
    int tid = threadIdx.x;
    int p1 = tid & 63, q1 = tid >> 6;
    int p2 = tid & 31, q2 = tid >> 5;

    // prologue: weight caches from inputs (safe pre-sync)
    u64 w1p[16], w2p[16];
    #pragma unroll
    for (int kk = 0; kk < 16; kk++) {
        int k = q1 * 16 + kk;
        w1p[kk] = pk2(__ldg(&W1[k * 128 + 2 * p1]), __ldg(&W1[k * 128 + 2 * p1 + 1]));
    }
    #pragma unroll
    for (int kk = 0; kk < 16; kk++) {
        int k = q2 * 16 + kk;
        w2p[kk] = pk2(__ldg(&W2[k * 64 + 2 * p2]), __ldg(&W2[k * 64 + 2 * p2 + 1]));
    }
    u64 bias1 = pk2(__ldg(&b1[2 * p1]), __ldg(&b1[2 * p1 + 1]));
    u64 bias2 = pk2(__ldg(&b2[2 * p2]), __ldg(&b2[2 * p2 + 1]));
    cudaGridDependencySynchronize();

    float2 lsum = make_float2(0.f, 0.f), lsq = make_float2(0.f, 0.f);

    for (int rq = blockIdx.x; rq < NN / 4; rq += gridDim.x) {
        int base = rq * 4;
        ((float*)rowf)[tid] = g_agg[(size_t)base * 64 + tid];
        __syncthreads();
        u64 a0 = 0ull, a1 = 0ull, a2 = 0ull, a3 = 0ull;
        #pragma unroll
        for (int kk = 0; kk < 16; kk++) {
            int k = q1 * 16 + kk;
            float r0 = rowf[0][k], r1 = rowf[1][k], r2 = rowf[2][k], r3 = rowf[3][k];
            a0 = f2fma(r0, w1p[kk], a0);
            a1 = f2fma(r1, w1p[kk], a1);
            a2 = f2fma(r2, w1p[kk], a2);
            a3 = f2fma(r3, w1p[kk], a3);
        }
        part[q1 * 256 + 0 * 64 + p1] = a0;
        part[q1 * 256 + 1 * 64 + p1] = a1;
        part[q1 * 256 + 2 * 64 + p1] = a2;
        part[q1 * 256 + 3 * 64 + p1] = a3;
        __syncthreads();
        {
            int rr = tid >> 6, pp = tid & 63;
            u64 s = add2(add2(part[0 * 256 + rr * 64 + pp], part[1 * 256 + rr * 64 + pp]),
                         add2(part[2 * 256 + rr * 64 + pp], part[3 * 256 + rr * 64 + pp]));
            float2 v = up2(add2(s, bias1));
            midf[rr][2 * pp]     = fmaxf(v.x, 0.f);
            midf[rr][2 * pp + 1] = fmaxf(v.y, 0.f);
        }
        __syncthreads();
        u64 c0 = 0ull, c1 = 0ull, c2 = 0ull, c3 = 0ull;
        #pragma unroll
        for (int kk = 0; kk < 16; kk++) {
            int k = q2 * 16 + kk;
            float m0 = midf[0][k], m1 = midf[1][k], m2 = midf[2][k], m3 = midf[3][k];
            c0 = f2fma(m0, w2p[kk], c0);
            c1 = f2fma(m1, w2p[kk], c1);
            c2 = f2fma(m2, w2p[kk], c2);
            c3 = f2fma(m3, w2p[kk], c3);
        }
        part[q2 * 128 + 0 * 32 + p2] = c0;
        part[q2 * 128 + 1 * 32 + p2] = c1;
        part[q2 * 128 + 2 * 32 + p2] = c2;
        part[q2 * 128 + 3 * 32 + p2] = c3;
        __syncthreads();
        if (tid < 128) {
            int rr = tid >> 5, pp = tid & 31;
            u64 s01 = add2(part[0 * 128 + rr * 32 + pp], part[1 * 128 + rr * 32 + pp]);
            u64 s23 = add2(part[2 * 128 + rr * 32 + pp], part[3 * 128 + rr * 32 + pp]);
            u64 s45 = add2(part[4 * 128 + rr * 32 + pp], part[5 * 128 + rr * 32 + pp]);
            u64 s67 = add2(part[6 * 128 + rr * 32 + pp], part[7 * 128 + rr * 32 + pp]);
            u64 s = add2(add2(s01, s23), add2(s45, s67));
            float2 v = up2(add2(s, bias2));
            *(float2*)(g_h2 + (size_t)(base + rr) * 64 + 2 * pp) = v;
            lsum.x += v.x; lsum.y += v.y;
            lsq.x += v.x * v.x; lsq.y += v.y * v.y;
        }
        __syncthreads();
    }
    if (tid < 128) {
        int pp = tid & 31;
        atomicAdd(&g_bnsumL[layer * 64 + 2 * pp], lsum.x);
        atomicAdd(&g_bnsumL[layer * 64 + 2 * pp + 1], lsum.y);
        atomicAdd(&g_bnsqL[layer * 64 + 2 * pp], lsq.x);
        atomicAdd(&g_bnsqL[layer * 64 + 2 * pp + 1], lsq.y);
    }
}

// ---------------- pools; which==0 applies final-layer BN on the fly ----------------
__global__ void k_pool(int which, const float* __restrict__ gamma,
                       const float* __restrict__ beta) {
    int b = blockIdx.x, t = threadIdx.x;
    if (which == 0) {
        float mu = g_bnsumL[(NL - 1) * 64 + t] * (1.f / (float)NN);
        float var = g_bnsqL[(NL - 1) * 64 + t] * (1.f / (float)NN) - mu * mu;
        float sc = gamma[t] * rsqrtf(var + FEPS);
        float sh = beta[t] - mu * sc;
        const float* p = g_h2 + (size_t)b * 200 * 64 + t;
        float s = 0.f;
        for (int r = 0; r < 200; r++) s += p[(size_t)r * 64];
        g_x1[b * 64 + t] = fmaf(sc, s * (1.f / 200.f), sh);
    } else {
        const float* p = g_xpf + (size_t)b * 400 * 64 + t;
        float s = 0.f;
        for (int r = 0; r < 400; r++) s += p[(size_t)r * 64];
        g_x2[b * 64 + t] = s * (1.f / 400.f);
    }
}

// ---------------- 2-set branch ----------------
__global__ void k_iso(const float* __restrict__ isoT) {
    int i = blockIdx.x * blockDim.x + threadIdx.x;
    if (i >= NN2) return;
    const float4* row = (const float4*)(isoT + (size_t)i * NNI2);
    int r = 0;
    #pragma unroll
    for (int q = 0; q < 9; q++) {
        float4 v = __ldg(&row[q]);
        if (v.x > 0.5f) r = 4 * q;
        if (v.y > 0.5f) r = 4 * q + 1;
        if (v.z > 0.5f) r = 4 * q + 2;
        if (v.w > 0.5f) r = 4 * q + 3;
    }
    g_iso[i] = r;
}

// proj: mode1 gathers assignment-pooled FINAL node rep from g_h2 with fused BN
__global__ __launch_bounds__(256) void k_proj(const float* __restrict__ Wrel,
                                              const float* __restrict__ Wroot,
                                              const int* __restrict__ asg,
                                              const float* __restrict__ gamma,
                                              const float* __restrict__ beta,
                                              int mode) {
    __shared__ __align__(16) float rowf[4][64];
    __shared__ u64 part[1024];
    __shared__ float isoWs[2 * NNI2 * 64];
    __shared__ float scs[64], shs[64];
    __shared__ int si[4];
    int tid = threadIdx.x;
    int m = tid >> 7;
    int rest = tid & 127;
    int p = rest & 31;
    int q = rest >> 5;
    const float* Wm = m ? Wroot : Wrel;

    // prologue: weights + iso table (inputs, safe pre-sync)
    u64 wp[16];
    #pragma unroll
    for (int kk = 0; kk < 16; kk++) {
        int k = q * 16 + kk;
        wp[kk] = pk2(__ldg(&Wm[k * 64 + 2 * p]), __ldg(&Wm[k * 64 + 2 * p + 1]));
    }
    if (mode) {
        for (int idx = tid; idx < 2 * NNI2 * 64; idx += 256) {
            int mm = idx / (NNI2 * 64);
            int rest2 = idx - mm * (NNI2 * 64);
            const float* Wx = mm ? Wroot : Wrel;
            isoWs[idx] = __ldg(&Wx[(64 + rest2 / 64) * 64 + (rest2 & 63)]);
        }
    }
    cudaGridDependencySynchronize();
    if (mode && tid < 64) {
        float mu = g_bnsumL[(NL - 1) * 64 + tid] * (1.f / (float)NN);
        float var = g_bnsqL[(NL - 1) * 64 + tid] * (1.f / (float)NN) - mu * mu;
        float s = gamma[tid] * rsqrtf(var + FEPS);
        scs[tid] = s;
        shs[tid] = beta[tid] - mu * s;
    }
    __syncthreads();

    for (int rq = blockIdx.x; rq < NN2 / 4; rq += gridDim.x) {
        int base = rq * 4;
        {
            int rr = tid >> 6, c = tid & 63;
            int i = base + rr;
            if (mode) {
                int a = __ldg(&asg[2 * i]);
                int b = __ldg(&asg[2 * i + 1]);
                float avg = 0.5f * (__ldg(&g_h2[(size_t)a * 64 + c]) +
                                    __ldg(&g_h2[(size_t)b * 64 + c]));
                rowf[rr][c] = fmaf(scs[c], avg, shs[c]);
                if (tid < 4) si[tid] = __ldg(&g_iso[base + tid]);
            } else {
                rowf[rr][c] = g_xpf[(size_t)i * 64 + c];
            }
        }
        __syncthreads();
        u64 a0 = 0ull, a1 = 0ull, a2 = 0ull, a3 = 0ull;
        #pragma unroll
        for (int kk = 0; kk < 16; kk++) {
            int k = q * 16 + kk;
            float r0 = rowf[0][k], r1 = rowf[1][k], r2 = rowf[2][k], r3 = rowf[3][k];
            a0 = f2fma(r0, wp[kk], a0);
            a1 = f2fma(r1, wp[kk], a1);
            a2 = f2fma(r2, wp[kk], a2);
            a3 = f2fma(r3, wp[kk], a3);
        }
        part[m * 512 + q * 128 + 0 * 32 + p] = a0;
        part[m * 512 + q * 128 + 1 * 32 + p] = a1;
        part[m * 512 + q * 128 + 2 * 32 + p] = a2;
        part[m * 512 + q * 128 + 3 * 32 + p] = a3;
        __syncthreads();
        {
            int mm = tid >> 7, rr = (tid >> 5) & 3, pp = tid & 31;
            u64 s = add2(add2(part[mm * 512 + 0 * 128 + rr * 32 + pp],
                              part[mm * 512 + 1 * 128 + rr * 32 + pp]),
                         add2(part[mm * 512 + 2 * 128 + rr * 32 + pp],
                              part[mm * 512 + 3 * 128 + rr * 32 + pp]));
            float2 v = up2(s);
            if (mode) {
                int is = si[rr];
                v.x += isoWs[mm * (NNI2 * 64) + is * 64 + 2 * pp];
                v.y += isoWs[mm * (NNI2 * 64) + is * 64 + 2 * pp + 1];
            }
            float* outp = mm ? g_zroot : g_zr;
            *(float2*)(outp + (size_t)(base + rr) * 64 + 2 * pp) = v;
        }
        __syncthreads();
    }
}

// conv aggregate: xpf[i] = relu( sum_{src} zr[src] + brel + zroot[i] )
__global__ __launch_bounds__(256) void k_cagg(const float* __restrict__ brel) {
    int warp = (blockIdx.x * blockDim.x + threadIdx.x) >> 5;
    int lane = threadIdx.x & 31;
    if (warp >= NN2) return;
    int n = warp;
    float2 z = __ldg((const float2*)(g_zroot + ((size_t)n << 6) + (lane << 1)));
    float ax0 = z.x + __ldg(&brel[2 * lane]);
    float ay0 = z.y + __ldg(&brel[2 * lane + 1]);
    float ax1 = 0.f, ay1 = 0.f;
    int beg = __ldg(&g_base2[n]);
    int end = beg + __ldg(&g_deg2[n]);
    int j = beg;
    for (; j + 32 <= end; j += 32) {
        int s = __ldg(&g_adj2[j + lane]);
        #pragma unroll
        for (int t = 0; t < 32; t++) {
            int src = __shfl_sync(0xffffffffu, s, t);
            float2 v = __ldg((const float2*)(g_zr + ((size_t)src << 6) + (lane << 1)));
            if (t & 1) { ax1 += v.x; ay1 += v.y; }
            else       { ax0 += v.x; ay0 += v.y; }
        }
    }
    if (j < end) {
        int idx = j + lane;
        int s = (idx < end) ? __ldg(&g_adj2[idx]) : 0;
        int c = end - j;
        for (int t = 0; t < c; t++) {
            int src = __shfl_sync(0xffffffffu, s, t);
            float2 v = __ldg((const float2*)(g_zr + ((size_t)src << 6) + (lane << 1)));
            if (t & 1) { ax1 += v.x; ay1 += v.y; }
            else       { ax0 += v.x; ay0 += v.y; }
        }
    }
    float2 o; o.x = fmaxf(ax0 + ax1, 0.f); o.y = fmaxf(ay0 + ay1, 0.f);
    *(float2*)(g_xpf + ((size_t)n << 6) + (lane << 1)) = o;
}

// ---------------- readout MLP ----------------
__global__ void k_readout(const float* __restrict__ W0, const float* __restrict__ b0,
                          const float* __restrict__ W1, const float* __restrict__ b1,
                          const float* __restrict__ W2, const float* __restrict__ b2,
                          const float* __restrict__ lW, const float* __restrict__ lb,
                          float* __restrict__ out) {
    __shared__ float m[128];
    __shared__ float h0[64];
    __shared__ float h1[32];
    __shared__ float h2s[16];
    int b = blockIdx.x, t = threadIdx.x;
    m[t] = g_x1[b * 64 + t];
    m[64 + t] = g_x2[b * 64 + t];
    __syncthreads();
    float acc = __ldg(&b0[t]);
    #pragma unroll 4
    for (int k = 0; k < 128; k++) acc = fmaf(m[k], __ldg(&W0[k * 64 + t]), acc);
    h0[t] = fmaxf(acc, 0.f);
    __syncthreads();
    if (t < 32) {
        float a = __ldg(&b1[t]);
        for (int k = 0; k < 64; k++) a = fmaf(h0[k], __ldg(&W1[k * 32 + t]), a);
        h1[t] = fmaxf(a, 0.f);
    }
    __syncthreads();
    if (t < 16) {
        float a = __ldg(&b2[t]);
        for (int k = 0; k < 32; k++) a = fmaf(h1[k], __ldg(&W2[k * 16 + t]), a);
        h2s[t] = fmaxf(a, 0.f);
    }
    __syncthreads();
    if (t == 0) {
        float a = __ldg(&lb[0]);
        for (int k = 0; k < 16; k++) a = fmaf(h2s[k], __ldg(&lW[k]), a);
        out[b] = a;
    }
}

// ---------------- launch ----------------
extern "C" void kernel_launch(void* const* d_in, const int* in_sizes, int n_in,
                              void* d_out, int out_size) {
    (void)in_sizes; (void)n_in; (void)out_size;
    const float* x    = (const float*)d_in[0];
    const int*   ei   = (const int*)d_in[1];
    const int*   ea   = (const int*)d_in[2];
    const float* isoT = (const float*)d_in[4];
    const int*   ei2  = (const int*)d_in[5];
    const int*   asg  = (const int*)d_in[6];
    const float* embW = (const float*)d_in[8];
    const float* embB = (const float*)d_in[9];
    const float* gW1  = (const float*)d_in[10];
    const float* gb1  = (const float*)d_in[11];
    const float* gW2  = (const float*)d_in[12];
    const float* gb2  = (const float*)d_in[13];
    const float* ee1  = (const float*)d_in[14];
    const float* ee2  = (const float*)d_in[15];
    const float* bng  = (const float*)d_in[16];
    const float* bnb  = (const float*)d_in[17];
    const float* i1rW = (const float*)d_in[18];
    const float* i1rb = (const float*)d_in[19];
    const float* i1oW = (const float*)d_in[20];
    const float* i2rW = (const float*)d_in[21];
    const float* i2rb = (const float*)d_in[22];
    const float* i2oW = (const float*)d_in[23];
    const float* rW0  = (const float*)d_in[24];
    const float* rb0  = (const float*)d_in[25];
    const float* rW1  = (const float*)d_in[26];
    const float* rb1  = (const float*)d_in[27];
    const float* rW2  = (const float*)d_in[28];
    const float* rb2  = (const float*)d_in[29];
    const float* lW   = (const float*)d_in[30];
    const float* lb   = (const float*)d_in[31];
    float* out = (float*)d_out;

    const float* bngL = bng + (size_t)(NL - 1) * ND;
    const float* bnbL = bnb + (size_t)(NL - 1) * ND;

    // ---- fork ----
    cudaEventRecord(g_hx.evRoot, 0);
    cudaStreamWaitEvent(g_hx.sB, g_hx.evRoot, 0);
    k_embed<<<2048, 128, 0, g_hx.sB>>>(x, embW, embB);
    cudaEventRecord(g_hx.evB, g_hx.sB);
    cudaStreamWaitEvent(g_hx.sC, g_hx.evRoot, 0);
    k_zero2<<<128, 256, 0, g_hx.sC>>>();
    k_count2<<<NE2 / 256, 256, 0, g_hx.sC>>>(ei2);
    k_reserve2<<<NN2 / 256, 256, 0, g_hx.sC>>>();
    k_fill2<<<NE2 / 256, 256, 0, g_hx.sC>>>(ei2);
    k_iso<<<(NN2 + 255) / 256, 256, 0, g_hx.sC>>>(isoT);
    cudaEventRecord(g_hx.evC, g_hx.sC);

    // ---- graph-1 CSR build (main stream) ----
    k_zero1<<<256, 256>>>();
    k_count1<<<NE / 256, 256>>>(ei, ea);
    k_reserve1<<<NN / 256, 256>>>();
    k_fill1<<<NE / 256, 256>>>(ei);

    // ---- join embed before first aggregation ----
    cudaStreamWaitEvent(0, g_hx.evB, 0);

    // ---- GIN stack (PDL-chained) ----
    for (int l = 0; l < NL; l++) {
        pdl_launch(k_agg1, dim3(NN / 8), dim3(256),
                   ee1 + (size_t)l * 6 * ND, ee2 + (size_t)l * 3 * ND,
                   bng + (size_t)(l > 0 ? l - 1 : 0) * ND,
                   bnb + (size_t)(l > 0 ? l - 1 : 0) * ND, l);
        pdl_launch(k_mlp, dim3(1280), dim3(256),
                   gW1 + (size_t)l * ND * 128, gb1 + (size_t)l * 128,
                   gW2 + (size_t)l * 128 * ND, gb2 + (size_t)l * ND, l);
    }

    // ---- fork: pool0 (reads g_h2 + final BN stats) concurrent with 2-set branch ----
    cudaEventRecord(g_hx.evRoot2, 0);
    cudaStreamWaitEvent(g_hx.sB, g_hx.evRoot2, 0);
    k_pool<<<NG, 64, 0, g_hx.sB>>>(0, bngL, bnbL);
    cudaEventRecord(g_hx.evB2, g_hx.sB);

    // ---- 2-set branch (join graph-2 CSR + iso first) ----
    cudaStreamWaitEvent(0, g_hx.evC, 0);
    pdl_launch(k_proj, dim3(1184), dim3(256), i1rW, i1oW, asg, bngL, bnbL, 1);
    k_cagg<<<NN2 / 8, 256>>>(i1rb);
    pdl_launch(k_proj, dim3(1184), dim3(256), i2rW, i2oW, asg, bngL, bnbL, 0);
    k_cagg<<<NN2 / 8, 256>>>(i2rb);
    k_pool<<<NG, 64>>>(1, bngL, bnbL);

    // ---- join pool0, then readout ----
    cudaStreamWaitEvent(0, g_hx.evB2, 0);
    k_readout<<<NG, 64>>>(rW0, rb0, rW1, rb1, rW2, rb2, lW, lb, out);
}

// round 15
// speedup vs baseline: 1.4825x; 1.4825x over previous
#include <cuda_runtime.h>
#include <cstdint>

#define NN   51200
#define NE   819200
#define NG   256
#define NN2  102400
#define NA   204800
#define NE2  409600
#define ND   64
#define NL   5
#define NNI2 36
#define NNAF 40
#define FEPS 1e-5f

typedef unsigned long long u64;

// ---------------- side streams for graph-level concurrency ----------------
struct HXStreams {
    cudaStream_t sB, sC;
    cudaEvent_t evRoot, evB, evC, evRoot2, evB2;
    HXStreams() {
        cudaStreamCreateWithFlags(&sB, cudaStreamNonBlocking);
        cudaStreamCreateWithFlags(&sC, cudaStreamNonBlocking);
        cudaEventCreateWithFlags(&evRoot,  cudaEventDisableTiming);
        cudaEventCreateWithFlags(&evB,     cudaEventDisableTiming);
        cudaEventCreateWithFlags(&evC,     cudaEventDisableTiming);
        cudaEventCreateWithFlags(&evRoot2, cudaEventDisableTiming);
        cudaEventCreateWithFlags(&evB2,    cudaEventDisableTiming);
    }
};
static HXStreams g_hx;

// ---------------- f32x2 packed helpers ----------------
__device__ __forceinline__ u64 pk2(float x, float y) {
    u64 r; asm("mov.b64 %0, {%1,%2};" : "=l"(r) : "f"(x), "f"(y)); return r;
}
__device__ __forceinline__ float2 up2(u64 v) {
    float2 r; asm("mov.b64 {%0,%1}, %2;" : "=f"(r.x), "=f"(r.y) : "l"(v)); return r;
}
__device__ __forceinline__ u64 f2fma(float a, u64 b, u64 c) {
    u64 d;
    asm("{\n\t.reg .b64 ra;\n\tmov.b64 ra, {%1,%1};\n\tfma.rn.f32x2 %0, ra, %2, %3;\n\t}"
        : "=l"(d) : "f"(a), "l"(b), "l"(c));
    return d;
}
__device__ __forceinline__ u64 add2(u64 a, u64 b) {
    u64 d; asm("add.rn.f32x2 %0, %1, %2;" : "=l"(d) : "l"(a), "l"(b)); return d;
}

// ---------------- device scratch ----------------
__device__ float g_h[NN * ND];      // embed output (layer-0 input)
__device__ float g_agg[NN * ND];
__device__ float g_h2[NN * ND];     // raw MLP output per layer (pre-BN)

__device__ int g_cnt12[NN * 12];
__device__ int g_deg1[NN];
__device__ int g_base1[NN];
__device__ int g_cursor1[NN];
__device__ int g_adj1[NE];
__device__ int g_total1;

__device__ int g_deg2[NN2];
__device__ int g_base2[NN2];
__device__ int g_cursor2[NN2];
__device__ int g_adj2[NE2];
__device__ int g_total2;

__device__ float g_xpf[NN2 * ND];
__device__ int   g_iso[NN2];
__device__ float g_zr[NN2 * ND];
__device__ float g_zroot[NN2 * ND];

__device__ float g_bnsumL[NL * ND];
__device__ float g_bnsqL[NL * ND];

__device__ float g_x1[NG * ND];
__device__ float g_x2[NG * ND];

// ---------------- zero ----------------
__global__ void k_zero1() {
    int i = blockIdx.x * blockDim.x + threadIdx.x;
    int stride = gridDim.x * blockDim.x;
    for (int j = i; j < NN * 12; j += stride) g_cnt12[j] = 0;
    for (int j = i; j < NL * ND; j += stride) { g_bnsumL[j] = 0.f; g_bnsqL[j] = 0.f; }
    if (i == 0) g_total1 = 0;
}
__global__ void k_zero2() {
    int i = blockIdx.x * blockDim.x + threadIdx.x;
    int stride = gridDim.x * blockDim.x;
    for (int j = i; j < NN2; j += stride) g_deg2[j] = 0;
    if (i == 0) g_total2 = 0;
}

// ---------------- counts ----------------
__global__ void k_count1(const int* __restrict__ ei, const int* __restrict__ ea) {
    int e = blockIdx.x * blockDim.x + threadIdx.x;
    if (e >= NE) return;
    int dst = ei[NE + e];
    int2 aa = __ldg((const int2*)(ea) + e);
    atomicAdd(&g_cnt12[dst * 12 + aa.x * 3 + aa.y], 1);
}
__global__ void k_count2(const int* __restrict__ ei2) {
    int e = blockIdx.x * blockDim.x + threadIdx.x;
    if (e >= NE2) return;
    atomicAdd(&g_deg2[ei2[NE2 + e]], 1);
}

// ---------------- reserve CSR ranges ----------------
__global__ void k_reserve1() {
    int i = blockIdx.x * blockDim.x + threadIdx.x;
    int lane = threadIdx.x & 31;
    if (i >= NN) return;
    int d = 0;
    #pragma unroll
    for (int c = 0; c < 12; c++) d += g_cnt12[i * 12 + c];
    g_deg1[i] = d;
    int incl = d;
    #pragma unroll
    for (int o = 1; o < 32; o <<= 1) {
        int t = __shfl_up_sync(0xffffffffu, incl, o);
        if (lane >= o) incl += t;
    }
    int tot = __shfl_sync(0xffffffffu, incl, 31);
    int base = 0;
    if (lane == 0) base = atomicAdd(&g_total1, tot);
    base = __shfl_sync(0xffffffffu, base, 0);
    int start = base + incl - d;
    g_base1[i] = start; g_cursor1[i] = start;
}
__global__ void k_reserve2() {
    int i = blockIdx.x * blockDim.x + threadIdx.x;
    int lane = threadIdx.x & 31;
    if (i >= NN2) return;
    int d = g_deg2[i];
    int incl = d;
    #pragma unroll
    for (int o = 1; o < 32; o <<= 1) {
        int t = __shfl_up_sync(0xffffffffu, incl, o);
        if (lane >= o) incl += t;
    }
    int tot = __shfl_sync(0xffffffffu, incl, 31);
    int base = 0;
    if (lane == 0) base = atomicAdd(&g_total2, tot);
    base = __shfl_sync(0xffffffffu, base, 0);
    int start = base + incl - d;
    g_base2[i] = start; g_cursor2[i] = start;
}

// ---------------- CSR fill ----------------
__global__ void k_fill1(const int* __restrict__ ei) {
    int e = blockIdx.x * blockDim.x + threadIdx.x;
    if (e >= NE) return;
    int dst = ei[NE + e];
    int pos = atomicAdd(&g_cursor1[dst], 1);
    g_adj1[pos] = ei[e];
}
__global__ void k_fill2(const int* __restrict__ ei2) {
    int e = blockIdx.x * blockDim.x + threadIdx.x;
    if (e >= NE2) return;
    int dst = ei2[NE2 + e];
    int pos = atomicAdd(&g_cursor2[dst], 1);
    g_adj2[pos] = ei2[e];
}

// ---------------- embed: h = relu(x @ embW + embB) ----------------
__global__ __launch_bounds__(128) void k_embed(const float* __restrict__ x,
                                               const float* __restrict__ W,
                                               const float* __restrict__ b) {
    __shared__ float Ws[NNAF * ND];
    __shared__ float bs[ND];
    __shared__ float row[2][NNAF];
    int tid = threadIdx.x;
    for (int i = tid; i < NNAF * ND; i += 128) Ws[i] = W[i];
    if (tid < 64) bs[tid] = b[tid];
    __syncthreads();
    int slot = tid >> 6, c = tid & 63;
    for (int base = blockIdx.x * 2; base < NN; base += gridDim.x * 2) {
        if (tid < 2 * NNAF) row[tid / NNAF][tid % NNAF] = x[(size_t)base * NNAF + tid];
        __syncthreads();
        float acc = bs[c];
        #pragma unroll
        for (int k = 0; k < NNAF; k++) acc = fmaf(row[slot][k], Ws[k * 64 + c], acc);
        g_h[(size_t)(base + slot) * 64 + c] = fmaxf(acc, 0.f);
        __syncthreads();
    }
}

// ---------------- GIN aggregation with fused BN+ReLU of the previous layer ----------------
__global__ __launch_bounds__(256) void k_agg1(const float* __restrict__ e1,
                                              const float* __restrict__ e2,
                                              const float* __restrict__ gammaP,
                                              const float* __restrict__ betaP,
                                              int layer) {
    const float* hsrc = (layer == 0) ? g_h : g_h2;
    __shared__ float comb[12][64];
    __shared__ float selfe[64];
    __shared__ float scs[64], shs[64];
    int tid = threadIdx.x;
    for (int idx = tid; idx < 12 * 64; idx += 256) {
        int cc = idx >> 6, d = idx & 63;
        comb[cc][d] = e1[(cc / 3) * 64 + d] + e2[(cc % 3) * 64 + d];
    }
    if (tid < 64) {
        selfe[tid] = e1[4 * 64 + tid] + e2[0 * 64 + tid];
        if (layer == 0) {
            scs[tid] = 1.f; shs[tid] = 0.f;
        } else {
            int pl = layer - 1;
            float mu = g_bnsumL[pl * 64 + tid] * (1.f / (float)NN);
            float var = g_bnsqL[pl * 64 + tid] * (1.f / (float)NN) - mu * mu;
            float s = gammaP[tid] * rsqrtf(var + FEPS);
            scs[tid] = s;
            shs[tid] = betaP[tid] - mu * s;
        }
    }
    __syncthreads();

    int warp = (blockIdx.x * 256 + tid) >> 5;
    if (warp >= NN) return;
    int n = warp;
    int lane = tid & 31;
    float scx = scs[2 * lane], scy = scs[2 * lane + 1];
    float shx = shs[2 * lane], shy = shs[2 * lane + 1];

    int cnt = (lane < 12) ? __ldg(&g_cnt12[n * 12 + lane]) : 0;

    float2 hv = __ldg((const float2*)(hsrc + ((size_t)n << 6) + (lane << 1)));
    float2 se = ((const float2*)selfe)[lane];
    float ax0 = fmaxf(fmaf(scx, hv.x, shx), 0.f) + se.x;
    float ay0 = fmaxf(fmaf(scy, hv.y, shy), 0.f) + se.y;
    float ax1 = 0.f, ay1 = 0.f;

    #pragma unroll
    for (int c = 0; c < 12; c++) {
        float cc = (float)__shfl_sync(0xffffffffu, cnt, c);
        float2 w = ((const float2*)comb[c])[lane];
        if (c & 1) { ax1 = fmaf(cc, w.x, ax1); ay1 = fmaf(cc, w.y, ay1); }
        else       { ax0 = fmaf(cc, w.x, ax0); ay0 = fmaf(cc, w.y, ay0); }
    }

    int beg = __ldg(&g_base1[n]);
    int end = beg + __ldg(&g_deg1[n]);
    int j = beg;
    for (; j + 32 <= end; j += 32) {
        int s = __ldg(&g_adj1[j + lane]);
        #pragma unroll
        for (int t = 0; t < 32; t++) {
            int src = __shfl_sync(0xffffffffu, s, t);
            float2 v = __ldg((const float2*)(hsrc + ((size_t)src << 6) + (lane << 1)));
            float vx = fmaxf(fmaf(scx, v.x, shx), 0.f);
            float vy = fmaxf(fmaf(scy, v.y, shy), 0.f);
            if (t & 1) { ax1 += vx; ay1 += vy; }
            else       { ax0 += vx; ay0 += vy; }
        }
    }
    if (j < end) {
        int idx = j + lane;
        int s = (idx < end) ? __ldg(&g_adj1[idx]) : 0;
        int c = end - j;
        for (int t = 0; t < c; t++) {
            int src = __shfl_sync(0xffffffffu, s, t);
            float2 v = __ldg((const float2*)(hsrc + ((size_t)src << 6) + (lane << 1)));
            float vx = fmaxf(fmaf(scx, v.x, shx), 0.f);
            float vy = fmaxf(fmaf(scy, v.y, shy), 0.f);
            if (t & 1) { ax1 += vx; ay1 += vy; }
            else       { ax0 += vx; ay0 += vy; }
        }
    }
    float2 o; o.x = ax0 + ax1; o.y = ay0 + ay1;
    *(float2*)(g_agg + ((size_t)n << 6) + (lane << 1)) = o;
}

// ---------------- GIN MLP v3: 4-row batch, K-split, ILP-4 ----------------
__global__ __launch_bounds__(256) void k_mlp(const float* __restrict__ W1,
                                             const float* __restrict__ b1,
                                             const float* __restrict__ W2,
                                             const float* __restrict__ b2,
                                             int layer) {
    __shared__ __align__(16) float rowf[4][64];
    __shared__ __align__(16) float midf[4][128];
    __shared__ u64 part[1024];
    int tid = threadIdx.x;
    int p1 = tid & 63, q1 = tid >> 6;
    int p2 = tid & 31, q2 = tid >> 5;

    u64 w1p[16], w2p[16];
    #pragma unroll
    for (int kk = 0; kk < 16; kk++) {
        int k = q1 * 16 + kk;
        w1p[kk] = pk2(__ldg(&W1[k * 128 + 2 * p1]), __ldg(&W1[k * 128 + 2 * p1 + 1]));
    }
    #pragma unroll
    for (int kk = 0; kk < 16; kk++) {
        int k = q2 * 16 + kk;
        w2p[kk] = pk2(__ldg(&W2[k * 64 + 2 * p2]), __ldg(&W2[k * 64 + 2 * p2 + 1]));
    }
    u64 bias1 = pk2(__ldg(&b1[2 * p1]), __ldg(&b1[2 * p1 + 1]));
    u64 bias2 = pk2(__ldg(&b2[2 * p2]), __ldg(&b2[2 * p2 + 1]));

    float2 lsum = make_float2(0.f, 0.f), lsq = make_float2(0.f, 0.f);

    for (int rq = blockIdx.x; rq < NN / 4; rq += gridDim.x) {
        int base = rq * 4;
        ((float*)rowf)[tid] = g_agg[(size_t)base * 64 + tid];
        __syncthreads();
        u64 a0 = 0ull, a1 = 0ull, a2 = 0ull, a3 = 0ull;
        #pragma unroll
        for (int kk = 0; kk < 16; kk++) {
            int k = q1 * 16 + kk;
            float r0 = rowf[0][k], r1 = rowf[1][k], r2 = rowf[2][k], r3 = rowf[3][k];
            a0 = f2fma(r0, w1p[kk], a0);
            a1 = f2fma(r1, w1p[kk], a1);
            a2 = f2fma(r2, w1p[kk], a2);
            a3 = f2fma(r3, w1p[kk], a3);
        }
        part[q1 * 256 + 0 * 64 + p1] = a0;
        part[q1 * 256 + 1 * 64 + p1] = a1;
        part[q1 * 256 + 2 * 64 + p1] = a2;
        part[q1 * 256 + 3 * 64 + p1] = a3;
        __syncthreads();
        {
            int rr = tid >> 6, pp = tid & 63;
            u64 s = add2(add2(part[0 * 256 + rr * 64 + pp], part[1 * 256 + rr * 64 + pp]),
                         add2(part[2 * 256 + rr * 64 + pp], part[3 * 256 + rr * 64 + pp]));
            float2 v = up2(add2(s, bias1));
            midf[rr][2 * pp]     = fmaxf(v.x, 0.f);
            midf[rr][2 * pp + 1] = fmaxf(v.y, 0.f);
        }
        __syncthreads();
        u64 c0 = 0ull, c1 = 0ull, c2 = 0ull, c3 = 0ull;
        #pragma unroll
        for (int kk = 0; kk < 16; kk++) {
            int k = q2 * 16 + kk;
            float m0 = midf[0][k], m1 = midf[1][k], m2 = midf[2][k], m3 = midf[3][k];
            c0 = f2fma(m0, w2p[kk], c0);
            c1 = f2fma(m1, w2p[kk], c1);
            c2 = f2fma(m2, w2p[kk], c2);
            c3 = f2fma(m3, w2p[kk], c3);
        }
        part[q2 * 128 + 0 * 32 + p2] = c0;
        part[q2 * 128 + 1 * 32 + p2] = c1;
        part[q2 * 128 + 2 * 32 + p2] = c2;
        part[q2 * 128 + 3 * 32 + p2] = c3;
        __syncthreads();
        if (tid < 128) {
            int rr = tid >> 5, pp = tid & 31;
            u64 s01 = add2(part[0 * 128 + rr * 32 + pp], part[1 * 128 + rr * 32 + pp]);
            u64 s23 = add2(part[2 * 128 + rr * 32 + pp], part[3 * 128 + rr * 32 + pp]);
            u64 s45 = add2(part[4 * 128 + rr * 32 + pp], part[5 * 128 + rr * 32 + pp]);
            u64 s67 = add2(part[6 * 128 + rr * 32 + pp], part[7 * 128 + rr * 32 + pp]);
            u64 s = add2(add2(s01, s23), add2(s45, s67));
            float2 v = up2(add2(s, bias2));
            *(float2*)(g_h2 + (size_t)(base + rr) * 64 + 2 * pp) = v;
            lsum.x += v.x; lsum.y += v.y;
            lsq.x += v.x * v.x; lsq.y += v.y * v.y;
        }
        __syncthreads();
    }
    if (tid < 128) {
        int pp = tid & 31;
        atomicAdd(&g_bnsumL[layer * 64 + 2 * pp], lsum.x);
        atomicAdd(&g_bnsumL[layer * 64 + 2 * pp + 1], lsum.y);
        atomicAdd(&g_bnsqL[layer * 64 + 2 * pp], lsq.x);
        atomicAdd(&g_bnsqL[layer * 64 + 2 * pp + 1], lsq.y);
    }
}

// ---------------- pools; which==0 applies final-layer BN on the fly ----------------
__global__ void k_pool(int which, const float* __restrict__ gamma,
                       const float* __restrict__ beta) {
    int b = blockIdx.x, t = threadIdx.x;
    if (which == 0) {
        float mu = g_bnsumL[(NL - 1) * 64 + t] * (1.f / (float)NN);
        float var = g_bnsqL[(NL - 1) * 64 + t] * (1.f / (float)NN) - mu * mu;
        float sc = gamma[t] * rsqrtf(var + FEPS);
        float sh = beta[t] - mu * sc;
        const float* p = g_h2 + (size_t)b * 200 * 64 + t;
        float s = 0.f;
        for (int r = 0; r < 200; r++) s += p[(size_t)r * 64];
        g_x1[b * 64 + t] = fmaf(sc, s * (1.f / 200.f), sh);
    } else {
        const float* p = g_xpf + (size_t)b * 400 * 64 + t;
        float s = 0.f;
        for (int r = 0; r < 400; r++) s += p[(size_t)r * 64];
        g_x2[b * 64 + t] = s * (1.f / 400.f);
    }
}

// ---------------- 2-set branch ----------------
__global__ void k_iso(const float* __restrict__ isoT) {
    int i = blockIdx.x * blockDim.x + threadIdx.x;
    if (i >= NN2) return;
    const float4* row = (const float4*)(isoT + (size_t)i * NNI2);
    int r = 0;
    #pragma unroll
    for (int q = 0; q < 9; q++) {
        float4 v = __ldg(&row[q]);
        if (v.x > 0.5f) r = 4 * q;
        if (v.y > 0.5f) r = 4 * q + 1;
        if (v.z > 0.5f) r = 4 * q + 2;
        if (v.w > 0.5f) r = 4 * q + 3;
    }
    g_iso[i] = r;
}

// proj: mode1 gathers assignment-pooled FINAL node rep from g_h2 with fused BN
__global__ __launch_bounds__(256) void k_proj(const float* __restrict__ Wrel,
                                              const float* __restrict__ Wroot,
                                              const int* __restrict__ asg,
                                              const float* __restrict__ gamma,
                                              const float* __restrict__ beta,
                                              int mode) {
    __shared__ __align__(16) float rowf[4][64];
    __shared__ u64 part[1024];
    __shared__ float isoWs[2 * NNI2 * 64];
    __shared__ float scs[64], shs[64];
    __shared__ int si[4];
    int tid = threadIdx.x;
    int m = tid >> 7;
    int rest = tid & 127;
    int p = rest & 31;
    int q = rest >> 5;
    const float* Wm = m ? Wroot : Wrel;

    u64 wp[16];
    #pragma unroll
    for (int kk = 0; kk < 16; kk++) {
        int k = q * 16 + kk;
        wp[kk] = pk2(__ldg(&Wm[k * 64 + 2 * p]), __ldg(&Wm[k * 64 + 2 * p + 1]));
    }
    if (mode) {
        for (int idx = tid; idx < 2 * NNI2 * 64; idx += 256) {
            int mm = idx / (NNI2 * 64);
            int rest2 = idx - mm * (NNI2 * 64);
            const float* Wx = mm ? Wroot : Wrel;
            isoWs[idx] = __ldg(&Wx[(64 + rest2 / 64) * 64 + (rest2 & 63)]);
        }
    }
    if (mode && tid < 64) {
        float mu = g_bnsumL[(NL - 1) * 64 + tid] * (1.f / (float)NN);
        float var = g_bnsqL[(NL - 1) * 64 + tid] * (1.f / (float)NN) - mu * mu;
        float s = gamma[tid] * rsqrtf(var + FEPS);
        scs[tid] = s;
        shs[tid] = beta[tid] - mu * s;
    }
    __syncthreads();

    for (int rq = blockIdx.x; rq < NN2 / 4; rq += gridDim.x) {
        int base = rq * 4;
        {
            int rr = tid >> 6, c = tid & 63;
            int i = base + rr;
            if (mode) {
                int a = __ldg(&asg[2 * i]);
                int b = __ldg(&asg[2 * i + 1]);
                float avg = 0.5f * (__ldg(&g_h2[(size_t)a * 64 + c]) +
                                    __ldg(&g_h2[(size_t)b * 64 + c]));
                rowf[rr][c] = fmaf(scs[c], avg, shs[c]);
                if (tid < 4) si[tid] = __ldg(&g_iso[base + tid]);
            } else {
                rowf[rr][c] = g_xpf[(size_t)i * 64 + c];
            }
        }
        __syncthreads();
        u64 a0 = 0ull, a1 = 0ull, a2 = 0ull, a3 = 0ull;
        #pragma unroll
        for (int kk = 0; kk < 16; kk++) {
            int k = q * 16 + kk;
            float r0 = rowf[0][k], r1 = rowf[1][k], r2 = rowf[2][k], r3 = rowf[3][k];
            a0 = f2fma(r0, wp[kk], a0);
            a1 = f2fma(r1, wp[kk], a1);
            a2 = f2fma(r2, wp[kk], a2);
            a3 = f2fma(r3, wp[kk], a3);
        }
        part[m * 512 + q * 128 + 0 * 32 + p] = a0;
        part[m * 512 + q * 128 + 1 * 32 + p] = a1;
        part[m * 512 + q * 128 + 2 * 32 + p] = a2;
        part[m * 512 + q * 128 + 3 * 32 + p] = a3;
        __syncthreads();
        {
            int mm = tid >> 7, rr = (tid >> 5) & 3, pp = tid & 31;
            u64 s = add2(add2(part[mm * 512 + 0 * 128 + rr * 32 + pp],
                              part[mm * 512 + 1 * 128 + rr * 32 + pp]),
                         add2(part[mm * 512 + 2 * 128 + rr * 32 + pp],
                              part[mm * 512 + 3 * 128 + rr * 32 + pp]));
            float2 v = up2(s);
            if (mode) {
                int is = si[rr];
                v.x += isoWs[mm * (NNI2 * 64) + is * 64 + 2 * pp];
                v.y += isoWs[mm * (NNI2 * 64) + is * 64 + 2 * pp + 1];
            }
            float* outp = mm ? g_zroot : g_zr;
            *(float2*)(outp + (size_t)(base + rr) * 64 + 2 * pp) = v;
        }
        __syncthreads();
    }
}

// conv aggregate: xpf[i] = relu( sum_{src} zr[src] + brel + zroot[i] )
__global__ __launch_bounds__(256) void k_cagg(const float* __restrict__ brel) {
    int warp = (blockIdx.x * blockDim.x + threadIdx.x) >> 5;
    int lane = threadIdx.x & 31;
    if (warp >= NN2) return;
    int n = warp;
    float2 z = __ldg((const float2*)(g_zroot + ((size_t)n << 6) + (lane << 1)));
    float ax0 = z.x + __ldg(&brel[2 * lane]);
    float ay0 = z.y + __ldg(&brel[2 * lane + 1]);
    float ax1 = 0.f, ay1 = 0.f;
    int beg = __ldg(&g_base2[n]);
    int end = beg + __ldg(&g_deg2[n]);
    int j = beg;
    for (; j + 32 <= end; j += 32) {
        int s = __ldg(&g_adj2[j + lane]);
        #pragma unroll
        for (int t = 0; t < 32; t++) {
            int src = __shfl_sync(0xffffffffu, s, t);
            float2 v = __ldg((const float2*)(g_zr + ((size_t)src << 6) + (lane << 1)));
            if (t & 1) { ax1 += v.x; ay1 += v.y; }
            else       { ax0 += v.x; ay0 += v.y; }
        }
    }
    if (j < end) {
        int idx = j + lane;
        int s = (idx < end) ? __ldg(&g_adj2[idx]) : 0;
        int c = end - j;
        for (int t = 0; t < c; t++) {
            int src = __shfl_sync(0xffffffffu, s, t);
            float2 v = __ldg((const float2*)(g_zr + ((size_t)src << 6) + (lane << 1)));
            if (t & 1) { ax1 += v.x; ay1 += v.y; }
            else       { ax0 += v.x; ay0 += v.y; }
        }
    }
    float2 o; o.x = fmaxf(ax0 + ax1, 0.f); o.y = fmaxf(ay0 + ay1, 0.f);
    *(float2*)(g_xpf + ((size_t)n << 6) + (lane << 1)) = o;
}

// ---------------- readout MLP ----------------
__global__ void k_readout(const float* __restrict__ W0, const float* __restrict__ b0,
                          const float* __restrict__ W1, const float* __restrict__ b1,
                          const float* __restrict__ W2, const float* __restrict__ b2,
                          const float* __restrict__ lW, const float* __restrict__ lb,
                          float* __restrict__ out) {
    __shared__ float m[128];
    __shared__ float h0[64];
    __shared__ float h1[32];
    __shared__ float h2s[16];
    int b = blockIdx.x, t = threadIdx.x;
    m[t] = g_x1[b * 64 + t];
    m[64 + t] = g_x2[b * 64 + t];
    __syncthreads();
    float acc = __ldg(&b0[t]);
    #pragma unroll 4
    for (int k = 0; k < 128; k++) acc = fmaf(m[k], __ldg(&W0[k * 64 + t]), acc);
    h0[t] = fmaxf(acc, 0.f);
    __syncthreads();
    if (t < 32) {
        float a = __ldg(&b1[t]);
        for (int k = 0; k < 64; k++) a = fmaf(h0[k], __ldg(&W1[k * 32 + t]), a);
        h1[t] = fmaxf(a, 0.f);
    }
    __syncthreads();
    if (t < 16) {
        float a = __ldg(&b2[t]);
        for (int k = 0; k < 32; k++) a = fmaf(h1[k], __ldg(&W2[k * 16 + t]), a);
        h2s[t] = fmaxf(a, 0.f);
    }
    __syncthreads();
    if (t == 0) {
        float a = __ldg(&lb[0]);
        for (int k = 0; k < 16; k++) a = fmaf(h2s[k], __ldg(&lW[k]), a);
        out[b] = a;
    }
}

// ---------------- launch ----------------
extern "C" void kernel_launch(void* const* d_in, const int* in_sizes, int n_in,
                              void* d_out, int out_size) {
    (void)in_sizes; (void)n_in; (void)out_size;
    const float* x    = (const float*)d_in[0];
    const int*   ei   = (const int*)d_in[1];
    const int*   ea   = (const int*)d_in[2];
    const float* isoT = (const float*)d_in[4];
    const int*   ei2  = (const int*)d_in[5];
    const int*   asg  = (const int*)d_in[6];
    const float* embW = (const float*)d_in[8];
    const float* embB = (const float*)d_in[9];
    const float* gW1  = (const float*)d_in[10];
    const float* gb1  = (const float*)d_in[11];
    const float* gW2  = (const float*)d_in[12];
    const float* gb2  = (const float*)d_in[13];
    const float* ee1  = (const float*)d_in[14];
    const float* ee2  = (const float*)d_in[15];
    const float* bng  = (const float*)d_in[16];
    const float* bnb  = (const float*)d_in[17];
    const float* i1rW = (const float*)d_in[18];
    const float* i1rb = (const float*)d_in[19];
    const float* i1oW = (const float*)d_in[20];
    const float* i2rW = (const float*)d_in[21];
    const float* i2rb = (const float*)d_in[22];
    const float* i2oW = (const float*)d_in[23];
    const float* rW0  = (const float*)d_in[24];
    const float* rb0  = (const float*)d_in[25];
    const float* rW1  = (const float*)d_in[26];
    const float* rb1  = (const float*)d_in[27];
    const float* rW2  = (const float*)d_in[28];
    const float* rb2  = (const float*)d_in[29];
    const float* lW   = (const float*)d_in[30];
    const float* lb   = (const float*)d_in[31];
    float* out = (float*)d_out;

    const float* bngL = bng + (size_t)(NL - 1) * ND;
    const float* bnbL = bnb + (size_t)(NL - 1) * ND;

    // ---- fork ----
    cudaEventRecord(g_hx.evRoot, 0);
    cudaStreamWaitEvent(g_hx.sB, g_hx.evRoot, 0);
    k_embed<<<2048, 128, 0, g_hx.sB>>>(x, embW, embB);
    cudaEventRecord(g_hx.evB, g_hx.sB);
    cudaStreamWaitEvent(g_hx.sC, g_hx.evRoot, 0);
    k_zero2<<<128, 256, 0, g_hx.sC>>>();
    k_count2<<<NE2 / 256, 256, 0, g_hx.sC>>>(ei2);
    k_reserve2<<<NN2 / 256, 256, 0, g_hx.sC>>>();
    k_fill2<<<NE2 / 256, 256, 0, g_hx.sC>>>(ei2);
    k_iso<<<(NN2 + 255) / 256, 256, 0, g_hx.sC>>>(isoT);
    cudaEventRecord(g_hx.evC, g_hx.sC);

    // ---- graph-1 CSR build (main stream) ----
    k_zero1<<<256, 256>>>();
    k_count1<<<NE / 256, 256>>>(ei, ea);
    k_reserve1<<<NN / 256, 256>>>();
    k_fill1<<<NE / 256, 256>>>(ei);

    // ---- join embed before first aggregation ----
    cudaStreamWaitEvent(0, g_hx.evB, 0);

    // ---- GIN stack: BN+ReLU of layer l-1 folded into agg of layer l ----
    for (int l = 0; l < NL; l++) {
        k_agg1<<<NN / 8, 256>>>(ee1 + (size_t)l * 6 * ND, ee2 + (size_t)l * 3 * ND,
                                bng + (size_t)(l > 0 ? l - 1 : 0) * ND,
                                bnb + (size_t)(l > 0 ? l - 1 : 0) * ND, l);
        k_mlp<<<1280, 256>>>(gW1 + (size_t)l * ND * 128, gb1 + (size_t)l * 128,
                             gW2 + (size_t)l * 128 * ND, gb2 + (size_t)l * ND, l);
    }

    // ---- fork: pool0 (reads g_h2 + final BN stats) concurrent with 2-set branch ----
    cudaEventRecord(g_hx.evRoot2, 0);
    cudaStreamWaitEvent(g_hx.sB, g_hx.evRoot2, 0);
    k_pool<<<NG, 64, 0, g_hx.sB>>>(0, bngL, bnbL);
    cudaEventRecord(g_hx.evB2, g_hx.sB);

    // ---- 2-set branch (join graph-2 CSR + iso first) ----
    cudaStreamWaitEvent(0, g_hx.evC, 0);
    k_proj<<<1184, 256>>>(i1rW, i1oW, asg, bngL, bnbL, 1);
    k_cagg<<<NN2 / 8, 256>>>(i1rb);
    k_proj<<<1184, 256>>>(i2rW, i2oW, asg, bngL, bnbL, 0);
    k_cagg<<<NN2 / 8, 256>>>(i2rb);
    k_pool<<<NG, 64>>>(1, bngL, bnbL);

    // ---- join pool0, then readout ----
    cudaStreamWaitEvent(0, g_hx.evB2, 0);
    k_readout<<<NG, 64>>>(rW0, rb0, rW1, rb1, rW2, rb2, lW, lb, out);
}

// round 16
// speedup vs baseline: 1.4905x; 1.0054x over previous
#include <cuda_runtime.h>
#include <cstdint>

#define NN   51200
#define NE   819200
#define NG   256
#define NN2  102400
#define NA   204800
#define NE2  409600
#define ND   64
#define NL   5
#define NNI2 36
#define NNAF 40
#define FEPS 1e-5f

typedef unsigned long long u64;

// ---------------- side streams for graph-level concurrency ----------------
struct HXStreams {
    cudaStream_t sB, sC;
    cudaEvent_t evRoot, evB, evC;
    HXStreams() {
        cudaStreamCreateWithFlags(&sB, cudaStreamNonBlocking);
        cudaStreamCreateWithFlags(&sC, cudaStreamNonBlocking);
        cudaEventCreateWithFlags(&evRoot, cudaEventDisableTiming);
        cudaEventCreateWithFlags(&evB,    cudaEventDisableTiming);
        cudaEventCreateWithFlags(&evC,    cudaEventDisableTiming);
    }
};
static HXStreams g_hx;

// ---------------- f32x2 packed helpers ----------------
__device__ __forceinline__ u64 pk2(float x, float y) {
    u64 r; asm("mov.b64 %0, {%1,%2};" : "=l"(r) : "f"(x), "f"(y)); return r;
}
__device__ __forceinline__ float2 up2(u64 v) {
    float2 r; asm("mov.b64 {%0,%1}, %2;" : "=f"(r.x), "=f"(r.y) : "l"(v)); return r;
}
// d = a*b + c, a scalar broadcast
__device__ __forceinline__ u64 f2fma(float a, u64 b, u64 c) {
    u64 d;
    asm("{\n\t.reg .b64 ra;\n\tmov.b64 ra, {%1,%1};\n\tfma.rn.f32x2 %0, ra, %2, %3;\n\t}"
        : "=l"(d) : "f"(a), "l"(b), "l"(c));
    return d;
}
// d = a*b + c, all packed
__device__ __forceinline__ u64 f2fma_vv(u64 a, u64 b, u64 c) {
    u64 d;
    asm("fma.rn.f32x2 %0, %1, %2, %3;" : "=l"(d) : "l"(a), "l"(b), "l"(c));
    return d;
}
__device__ __forceinline__ u64 add2(u64 a, u64 b) {
    u64 d; asm("add.rn.f32x2 %0, %1, %2;" : "=l"(d) : "l"(a), "l"(b)); return d;
}

// ---------------- device scratch ----------------
__device__ float g_h[NN * ND];      // embed output (layer-0 input)
__device__ float g_agg[NN * ND];
__device__ float g_h2[NN * ND];     // raw MLP output per layer (pre-BN)

__device__ int g_cnt12[NN * 12];
__device__ int g_deg1[NN];
__device__ int g_base1[NN];
__device__ int g_cursor1[NN];
__device__ int g_adj1[NE];
__device__ int g_total1;

__device__ int g_deg2[NN2];
__device__ int g_base2[NN2];
__device__ int g_cursor2[NN2];
__device__ int g_adj2[NE2];
__device__ int g_total2;

__device__ float g_xpf[NN2 * ND];
__device__ int   g_iso[NN2];
__device__ float g_zr[NN2 * ND];
__device__ float g_zroot[NN2 * ND];

__device__ float g_bnsumL[NL * ND];
__device__ float g_bnsqL[NL * ND];

// ---------------- zero ----------------
__global__ void k_zero1() {
    int i = blockIdx.x * blockDim.x + threadIdx.x;
    int stride = gridDim.x * blockDim.x;
    for (int j = i; j < NN * 12; j += stride) g_cnt12[j] = 0;
    for (int j = i; j < NL * ND; j += stride) { g_bnsumL[j] = 0.f; g_bnsqL[j] = 0.f; }
    if (i == 0) g_total1 = 0;
}
__global__ void k_zero2() {
    int i = blockIdx.x * blockDim.x + threadIdx.x;
    int stride = gridDim.x * blockDim.x;
    for (int j = i; j < NN2; j += stride) g_deg2[j] = 0;
    if (i == 0) g_total2 = 0;
}

// ---------------- counts ----------------
__global__ void k_count1(const int* __restrict__ ei, const int* __restrict__ ea) {
    int e = blockIdx.x * blockDim.x + threadIdx.x;
    if (e >= NE) return;
    int dst = ei[NE + e];
    int2 aa = __ldg((const int2*)(ea) + e);
    atomicAdd(&g_cnt12[dst * 12 + aa.x * 3 + aa.y], 1);
}
__global__ void k_count2(const int* __restrict__ ei2) {
    int e = blockIdx.x * blockDim.x + threadIdx.x;
    if (e >= NE2) return;
    atomicAdd(&g_deg2[ei2[NE2 + e]], 1);
}

// ---------------- reserve CSR ranges ----------------
__global__ void k_reserve1() {
    int i = blockIdx.x * blockDim.x + threadIdx.x;
    int lane = threadIdx.x & 31;
    if (i >= NN) return;
    int d = 0;
    #pragma unroll
    for (int c = 0; c < 12; c++) d += g_cnt12[i * 12 + c];
    g_deg1[i] = d;
    int incl = d;
    #pragma unroll
    for (int o = 1; o < 32; o <<= 1) {
        int t = __shfl_up_sync(0xffffffffu, incl, o);
        if (lane >= o) incl += t;
    }
    int tot = __shfl_sync(0xffffffffu, incl, 31);
    int base = 0;
    if (lane == 0) base = atomicAdd(&g_total1, tot);
    base = __shfl_sync(0xffffffffu, base, 0);
    int start = base + incl - d;
    g_base1[i] = start; g_cursor1[i] = start;
}
__global__ void k_reserve2() {
    int i = blockIdx.x * blockDim.x + threadIdx.x;
    int lane = threadIdx.x & 31;
    if (i >= NN2) return;
    int d = g_deg2[i];
    int incl = d;
    #pragma unroll
    for (int o = 1; o < 32; o <<= 1) {
        int t = __shfl_up_sync(0xffffffffu, incl, o);
        if (lane >= o) incl += t;
    }
    int tot = __shfl_sync(0xffffffffu, incl, 31);
    int base = 0;
    if (lane == 0) base = atomicAdd(&g_total2, tot);
    base = __shfl_sync(0xffffffffu, base, 0);
    int start = base + incl - d;
    g_base2[i] = start; g_cursor2[i] = start;
}

// ---------------- CSR fill ----------------
__global__ void k_fill1(const int* __restrict__ ei) {
    int e = blockIdx.x * blockDim.x + threadIdx.x;
    if (e >= NE) return;
    int dst = ei[NE + e];
    int pos = atomicAdd(&g_cursor1[dst], 1);
    g_adj1[pos] = ei[e];
}
__global__ void k_fill2(const int* __restrict__ ei2) {
    int e = blockIdx.x * blockDim.x + threadIdx.x;
    if (e >= NE2) return;
    int dst = ei2[NE2 + e];
    int pos = atomicAdd(&g_cursor2[dst], 1);
    g_adj2[pos] = ei2[e];
}

// ---------------- embed: h = relu(x @ embW + embB) ----------------
__global__ __launch_bounds__(128) void k_embed(const float* __restrict__ x,
                                               const float* __restrict__ W,
                                               const float* __restrict__ b) {
    __shared__ float Ws[NNAF * ND];
    __shared__ float bs[ND];
    __shared__ float row[2][NNAF];
    int tid = threadIdx.x;
    for (int i = tid; i < NNAF * ND; i += 128) Ws[i] = W[i];
    if (tid < 64) bs[tid] = b[tid];
    __syncthreads();
    int slot = tid >> 6, c = tid & 63;
    for (int base = blockIdx.x * 2; base < NN; base += gridDim.x * 2) {
        if (tid < 2 * NNAF) row[tid / NNAF][tid % NNAF] = x[(size_t)base * NNAF + tid];
        __syncthreads();
        float acc = bs[c];
        #pragma unroll
        for (int k = 0; k < NNAF; k++) acc = fmaf(row[slot][k], Ws[k * 64 + c], acc);
        g_h[(size_t)(base + slot) * 64 + c] = fmaxf(acc, 0.f);
        __syncthreads();
    }
}

// ---------------- GIN aggregation, fused BN+ReLU, packed f32x2 inner loop ----------------
__global__ __launch_bounds__(256) void k_agg1(const float* __restrict__ e1,
                                              const float* __restrict__ e2,
                                              const float* __restrict__ gammaP,
                                              const float* __restrict__ betaP,
                                              int layer) {
    const float* hsrc = (layer == 0) ? g_h : g_h2;
    __shared__ float comb[12][64];
    __shared__ float selfe[64];
    __shared__ float scs[64], shs[64];
    int tid = threadIdx.x;
    for (int idx = tid; idx < 12 * 64; idx += 256) {
        int cc = idx >> 6, d = idx & 63;
        comb[cc][d] = e1[(cc / 3) * 64 + d] + e2[(cc % 3) * 64 + d];
    }
    if (tid < 64) {
        selfe[tid] = e1[4 * 64 + tid] + e2[0 * 64 + tid];
        if (layer == 0) {
            scs[tid] = 1.f; shs[tid] = 0.f;
        } else {
            int pl = layer - 1;
            float mu = g_bnsumL[pl * 64 + tid] * (1.f / (float)NN);
            float var = g_bnsqL[pl * 64 + tid] * (1.f / (float)NN) - mu * mu;
            float s = gammaP[tid] * rsqrtf(var + FEPS);
            scs[tid] = s;
            shs[tid] = betaP[tid] - mu * s;
        }
    }
    __syncthreads();

    int warp = (blockIdx.x * 256 + tid) >> 5;
    if (warp >= NN) return;
    int n = warp;
    int lane = tid & 31;
    u64 scp = pk2(scs[2 * lane], scs[2 * lane + 1]);
    u64 shp = pk2(shs[2 * lane], shs[2 * lane + 1]);

    int cnt = (lane < 12) ? __ldg(&g_cnt12[n * 12 + lane]) : 0;

    // scalar preamble: self term (BN-transformed) + edge-embed counts
    float sx, sy;
    {
        u64 hv = __ldg((const u64*)(hsrc + ((size_t)n << 6) + (lane << 1)));
        float2 f = up2(f2fma_vv(scp, hv, shp));
        float2 se = ((const float2*)selfe)[lane];
        sx = fmaxf(f.x, 0.f) + se.x;
        sy = fmaxf(f.y, 0.f) + se.y;
        #pragma unroll
        for (int c = 0; c < 12; c++) {
            float cc = (float)__shfl_sync(0xffffffffu, cnt, c);
            float2 w = ((const float2*)comb[c])[lane];
            sx = fmaf(cc, w.x, sx);
            sy = fmaf(cc, w.y, sy);
        }
    }

    // packed gather loop
    u64 a0 = 0ull, a1 = 0ull;
    int beg = __ldg(&g_base1[n]);
    int end = beg + __ldg(&g_deg1[n]);
    int j = beg;
    for (; j + 32 <= end; j += 32) {
        int s = __ldg(&g_adj1[j + lane]);
        #pragma unroll
        for (int t = 0; t < 32; t++) {
            int src = __shfl_sync(0xffffffffu, s, t);
            u64 v = __ldg((const u64*)(hsrc + ((size_t)src << 6) + (lane << 1)));
            float2 f = up2(f2fma_vv(scp, v, shp));
            u64 r = pk2(fmaxf(f.x, 0.f), fmaxf(f.y, 0.f));
            if (t & 1) a1 = add2(a1, r);
            else       a0 = add2(a0, r);
        }
    }
    if (j < end) {
        int idx = j + lane;
        int s = (idx < end) ? __ldg(&g_adj1[idx]) : 0;
        int c = end - j;
        for (int t = 0; t < c; t++) {
            int src = __shfl_sync(0xffffffffu, s, t);
            u64 v = __ldg((const u64*)(hsrc + ((size_t)src << 6) + (lane << 1)));
            float2 f = up2(f2fma_vv(scp, v, shp));
            u64 r = pk2(fmaxf(f.x, 0.f), fmaxf(f.y, 0.f));
            if (t & 1) a1 = add2(a1, r);
            else       a0 = add2(a0, r);
        }
    }
    float2 o = up2(add2(a0, a1));
    o.x += sx; o.y += sy;
    *(float2*)(g_agg + ((size_t)n << 6) + (lane << 1)) = o;
}

// ---------------- GIN MLP v3: 4-row batch, K-split, ILP-4 ----------------
__global__ __launch_bounds__(256) void k_mlp(const float* __restrict__ W1,
                                             const float* __restrict__ b1,
                                             const float* __restrict__ W2,
                                             const float* __restrict__ b2,
                                             int layer) {
    __shared__ __align__(16) float rowf[4][64];
    __shared__ __align__(16) float midf[4][128];
    __shared__ u64 part[1024];
    int tid = threadIdx.x;
    int p1 = tid & 63, q1 = tid >> 6;
    int p2 = tid & 31, q2 = tid >> 5;

    u64 w1p[16], w2p[16];
    #pragma unroll
    for (int kk = 0; kk < 16; kk++) {
        int k = q1 * 16 + kk;
        w1p[kk] = pk2(__ldg(&W1[k * 128 + 2 * p1]), __ldg(&W1[k * 128 + 2 * p1 + 1]));
    }
    #pragma unroll
    for (int kk = 0; kk < 16; kk++) {
        int k = q2 * 16 + kk;
        w2p[kk] = pk2(__ldg(&W2[k * 64 + 2 * p2]), __ldg(&W2[k * 64 + 2 * p2 + 1]));
    }
    u64 bias1 = pk2(__ldg(&b1[2 * p1]), __ldg(&b1[2 * p1 + 1]));
    u64 bias2 = pk2(__ldg(&b2[2 * p2]), __ldg(&b2[2 * p2 + 1]));

    float2 lsum = make_float2(0.f, 0.f), lsq = make_float2(0.f, 0.f);

    for (int rq = blockIdx.x; rq < NN / 4; rq += gridDim.x) {
        int base = rq * 4;
        ((float*)rowf)[tid] = g_agg[(size_t)base * 64 + tid];
        __syncthreads();
        u64 a0 = 0ull, a1 = 0ull, a2 = 0ull, a3 = 0ull;
        #pragma unroll
        for (int kk = 0; kk < 16; kk++) {
            int k = q1 * 16 + kk;
            float r0 = rowf[0][k], r1 = rowf[1][k], r2 = rowf[2][k], r3 = rowf[3][k];
            a0 = f2fma(r0, w1p[kk], a0);
            a1 = f2fma(r1, w1p[kk], a1);
            a2 = f2fma(r2, w1p[kk], a2);
            a3 = f2fma(r3, w1p[kk], a3);
        }
        part[q1 * 256 + 0 * 64 + p1] = a0;
        part[q1 * 256 + 1 * 64 + p1] = a1;
        part[q1 * 256 + 2 * 64 + p1] = a2;
        part[q1 * 256 + 3 * 64 + p1] = a3;
        __syncthreads();
        {
            int rr = tid >> 6, pp = tid & 63;
            u64 s = add2(add2(part[0 * 256 + rr * 64 + pp], part[1 * 256 + rr * 64 + pp]),
                         add2(part[2 * 256 + rr * 64 + pp], part[3 * 256 + rr * 64 + pp]));
            float2 v = up2(add2(s, bias1));
            midf[rr][2 * pp]     = fmaxf(v.x, 0.f);
            midf[rr][2 * pp + 1] = fmaxf(v.y, 0.f);
        }
        __syncthreads();
        u64 c0 = 0ull, c1 = 0ull, c2 = 0ull, c3 = 0ull;
        #pragma unroll
        for (int kk = 0; kk < 16; kk++) {
            int k = q2 * 16 + kk;
            float m0 = midf[0][k], m1 = midf[1][k], m2 = midf[2][k], m3 = midf[3][k];
            c0 = f2fma(m0, w2p[kk], c0);
            c1 = f2fma(m1, w2p[kk], c1);
            c2 = f2fma(m2, w2p[kk], c2);
            c3 = f2fma(m3, w2p[kk], c3);
        }
        part[q2 * 128 + 0 * 32 + p2] = c0;
        part[q2 * 128 + 1 * 32 + p2] = c1;
        part[q2 * 128 + 2 * 32 + p2] = c2;
        part[q2 * 128 + 3 * 32 + p2] = c3;
        __syncthreads();
        if (tid < 128) {
            int rr = tid >> 5, pp = tid & 31;
            u64 s01 = add2(part[0 * 128 + rr * 32 + pp], part[1 * 128 + rr * 32 + pp]);
            u64 s23 = add2(part[2 * 128 + rr * 32 + pp], part[3 * 128 + rr * 32 + pp]);
            u64 s45 = add2(part[4 * 128 + rr * 32 + pp], part[5 * 128 + rr * 32 + pp]);
            u64 s67 = add2(part[6 * 128 + rr * 32 + pp], part[7 * 128 + rr * 32 + pp]);
            u64 s = add2(add2(s01, s23), add2(s45, s67));
            float2 v = up2(add2(s, bias2));
            *(float2*)(g_h2 + (size_t)(base + rr) * 64 + 2 * pp) = v;
            lsum.x += v.x; lsum.y += v.y;
            lsq.x += v.x * v.x; lsq.y += v.y * v.y;
        }
        __syncthreads();
    }
    if (tid < 128) {
        int pp = tid & 31;
        atomicAdd(&g_bnsumL[layer * 64 + 2 * pp], lsum.x);
        atomicAdd(&g_bnsumL[layer * 64 + 2 * pp + 1], lsum.y);
        atomicAdd(&g_bnsqL[layer * 64 + 2 * pp], lsq.x);
        atomicAdd(&g_bnsqL[layer * 64 + 2 * pp + 1], lsq.y);
    }
}

// ---------------- 2-set branch ----------------
__global__ void k_iso(const float* __restrict__ isoT) {
    int i = blockIdx.x * blockDim.x + threadIdx.x;
    if (i >= NN2) return;
    const float4* row = (const float4*)(isoT + (size_t)i * NNI2);
    int r = 0;
    #pragma unroll
    for (int q = 0; q < 9; q++) {
        float4 v = __ldg(&row[q]);
        if (v.x > 0.5f) r = 4 * q;
        if (v.y > 0.5f) r = 4 * q + 1;
        if (v.z > 0.5f) r = 4 * q + 2;
        if (v.w > 0.5f) r = 4 * q + 3;
    }
    g_iso[i] = r;
}

// proj: mode1 gathers assignment-pooled FINAL node rep from g_h2 with fused BN
__global__ __launch_bounds__(256) void k_proj(const float* __restrict__ Wrel,
                                              const float* __restrict__ Wroot,
                                              const int* __restrict__ asg,
                                              const float* __restrict__ gamma,
                                              const float* __restrict__ beta,
                                              int mode) {
    __shared__ __align__(16) float rowf[4][64];
    __shared__ u64 part[1024];
    __shared__ float isoWs[2 * NNI2 * 64];
    __shared__ float scs[64], shs[64];
    __shared__ int si[4];
    int tid = threadIdx.x;
    int m = tid >> 7;
    int rest = tid & 127;
    int p = rest & 31;
    int q = rest >> 5;
    const float* Wm = m ? Wroot : Wrel;

    u64 wp[16];
    #pragma unroll
    for (int kk = 0; kk < 16; kk++) {
        int k = q * 16 + kk;
        wp[kk] = pk2(__ldg(&Wm[k * 64 + 2 * p]), __ldg(&Wm[k * 64 + 2 * p + 1]));
    }
    if (mode) {
        for (int idx = tid; idx < 2 * NNI2 * 64; idx += 256) {
            int mm = idx / (NNI2 * 64);
            int rest2 = idx - mm * (NNI2 * 64);
            const float* Wx = mm ? Wroot : Wrel;
            isoWs[idx] = __ldg(&Wx[(64 + rest2 / 64) * 64 + (rest2 & 63)]);
        }
    }
    if (mode && tid < 64) {
        float mu = g_bnsumL[(NL - 1) * 64 + tid] * (1.f / (float)NN);
        float var = g_bnsqL[(NL - 1) * 64 + tid] * (1.f / (float)NN) - mu * mu;
        float s = gamma[tid] * rsqrtf(var + FEPS);
        scs[tid] = s;
        shs[tid] = beta[tid] - mu * s;
    }
    __syncthreads();

    for (int rq = blockIdx.x; rq < NN2 / 4; rq += gridDim.x) {
        int base = rq * 4;
        {
            int rr = tid >> 6, c = tid & 63;
            int i = base + rr;
            if (mode) {
                int a = __ldg(&asg[2 * i]);
                int b = __ldg(&asg[2 * i + 1]);
                float avg = 0.5f * (__ldg(&g_h2[(size_t)a * 64 + c]) +
                                    __ldg(&g_h2[(size_t)b * 64 + c]));
                rowf[rr][c] = fmaf(scs[c], avg, shs[c]);
                if (tid < 4) si[tid] = __ldg(&g_iso[base + tid]);
            } else {
                rowf[rr][c] = g_xpf[(size_t)i * 64 + c];
            }
        }
        __syncthreads();
        u64 a0 = 0ull, a1 = 0ull, a2 = 0ull, a3 = 0ull;
        #pragma unroll
        for (int kk = 0; kk < 16; kk++) {
            int k = q * 16 + kk;
            float r0 = rowf[0][k], r1 = rowf[1][k], r2 = rowf[2][k], r3 = rowf[3][k];
            a0 = f2fma(r0, wp[kk], a0);
            a1 = f2fma(r1, wp[kk], a1);
            a2 = f2fma(r2, wp[kk], a2);
            a3 = f2fma(r3, wp[kk], a3);
        }
        part[m * 512 + q * 128 + 0 * 32 + p] = a0;
        part[m * 512 + q * 128 + 1 * 32 + p] = a1;
        part[m * 512 + q * 128 + 2 * 32 + p] = a2;
        part[m * 512 + q * 128 + 3 * 32 + p] = a3;
        __syncthreads();
        {
            int mm = tid >> 7, rr = (tid >> 5) & 3, pp = tid & 31;
            u64 s = add2(add2(part[mm * 512 + 0 * 128 + rr * 32 + pp],
                              part[mm * 512 + 1 * 128 + rr * 32 + pp]),
                         add2(part[mm * 512 + 2 * 128 + rr * 32 + pp],
                              part[mm * 512 + 3 * 128 + rr * 32 + pp]));
            float2 v = up2(s);
            if (mode) {
                int is = si[rr];
                v.x += isoWs[mm * (NNI2 * 64) + is * 64 + 2 * pp];
                v.y += isoWs[mm * (NNI2 * 64) + is * 64 + 2 * pp + 1];
            }
            float* outp = mm ? g_zroot : g_zr;
            *(float2*)(outp + (size_t)(base + rr) * 64 + 2 * pp) = v;
        }
        __syncthreads();
    }
}

// conv aggregate, packed accumulation
__global__ __launch_bounds__(256) void k_cagg(const float* __restrict__ brel) {
    int warp = (blockIdx.x * blockDim.x + threadIdx.x) >> 5;
    int lane = threadIdx.x & 31;
    if (warp >= NN2) return;
    int n = warp;
    float2 z = __ldg((const float2*)(g_zroot + ((size_t)n << 6) + (lane << 1)));
    float bx = z.x + __ldg(&brel[2 * lane]);
    float by = z.y + __ldg(&brel[2 * lane + 1]);
    u64 a0 = 0ull, a1 = 0ull;
    int beg = __ldg(&g_base2[n]);
    int end = beg + __ldg(&g_deg2[n]);
    int j = beg;
    for (; j + 32 <= end; j += 32) {
        int s = __ldg(&g_adj2[j + lane]);
        #pragma unroll
        for (int t = 0; t < 32; t++) {
            int src = __shfl_sync(0xffffffffu, s, t);
            u64 v = __ldg((const u64*)(g_zr + ((size_t)src << 6) + (lane << 1)));
            if (t & 1) a1 = add2(a1, v);
            else       a0 = add2(a0, v);
        }
    }
    if (j < end) {
        int idx = j + lane;
        int s = (idx < end) ? __ldg(&g_adj2[idx]) : 0;
        int c = end - j;
        for (int t = 0; t < c; t++) {
            int src = __shfl_sync(0xffffffffu, s, t);
            u64 v = __ldg((const u64*)(g_zr + ((size_t)src << 6) + (lane << 1)));
            if (t & 1) a1 = add2(a1, v);
            else       a0 = add2(a0, v);
        }
    }
    float2 f = up2(add2(a0, a1));
    float2 o;
    o.x = fmaxf(bx + f.x, 0.f);
    o.y = fmaxf(by + f.y, 0.f);
    *(float2*)(g_xpf + ((size_t)n << 6) + (lane << 1)) = o;
}

// ---------------- fused pools + readout ----------------
__global__ __launch_bounds__(256) void k_tail(const float* __restrict__ gamma,
                                              const float* __restrict__ beta,
                                              const float* __restrict__ W0,
                                              const float* __restrict__ b0,
                                              const float* __restrict__ W1,
                                              const float* __restrict__ b1,
                                              const float* __restrict__ W2,
                                              const float* __restrict__ b2,
                                              const float* __restrict__ lW,
                                              const float* __restrict__ lb,
                                              float* __restrict__ out) {
    __shared__ float red[256];
    __shared__ float m[128];
    __shared__ float h0[64];
    __shared__ float h1[32];
    __shared__ float h2s[16];
    int b = blockIdx.x, tid = threadIdx.x;
    int c = tid & 63, rs = tid >> 6;
    // pool0 over raw final-layer output with BN applied to the mean
    {
        const float* p = g_h2 + (size_t)b * 200 * 64 + c;
        float s = 0.f;
        for (int r = rs; r < 200; r += 4) s += p[(size_t)r * 64];
        red[rs * 64 + c] = s;
    }
    __syncthreads();
    if (tid < 64) {
        float mu = g_bnsumL[(NL - 1) * 64 + tid] * (1.f / (float)NN);
        float var = g_bnsqL[(NL - 1) * 64 + tid] * (1.f / (float)NN) - mu * mu;
        float sc = gamma[tid] * rsqrtf(var + FEPS);
        float sh = beta[tid] - mu * sc;
        float t = red[tid] + red[64 + tid] + red[128 + tid] + red[192 + tid];
        m[tid] = fmaf(sc, t * (1.f / 200.f), sh);
    }
    __syncthreads();
    // pool1
    {
        const float* p = g_xpf + (size_t)b * 400 * 64 + c;
        float s = 0.f;
        for (int r = rs; r < 400; r += 4) s += p[(size_t)r * 64];
        red[rs * 64 + c] = s;
    }
    __syncthreads();
    if (tid < 64) {
        float t = red[tid] + red[64 + tid] + red[128 + tid] + red[192 + tid];
        m[64 + tid] = t * (1.f / 400.f);
    }
    __syncthreads();
    // readout MLP on 64 threads
    if (tid < 64) {
        float acc = __ldg(&b0[tid]);
        #pragma unroll 4
        for (int k = 0; k < 128; k++) acc = fmaf(m[k], __ldg(&W0[k * 64 + tid]), acc);
        h0[tid] = fmaxf(acc, 0.f);
    }
    __syncthreads();
    if (tid < 32) {
        float a = __ldg(&b1[tid]);
        for (int k = 0; k < 64; k++) a = fmaf(h0[k], __ldg(&W1[k * 32 + tid]), a);
        h1[tid] = fmaxf(a, 0.f);
    }
    __syncthreads();
    if (tid < 16) {
        float a = __ldg(&b2[tid]);
        for (int k = 0; k < 32; k++) a = fmaf(h1[k], __ldg(&W2[k * 16 + tid]), a);
        h2s[tid] = fmaxf(a, 0.f);
    }
    __syncthreads();
    if (tid == 0) {
        float a = __ldg(&lb[0]);
        for (int k = 0; k < 16; k++) a = fmaf(h2s[k], __ldg(&lW[k]), a);
        out[b] = a;
    }
}

// ---------------- launch ----------------
extern "C" void kernel_launch(void* const* d_in, const int* in_sizes, int n_in,
                              void* d_out, int out_size) {
    (void)in_sizes; (void)n_in; (void)out_size;
    const float* x    = (const float*)d_in[0];
    const int*   ei   = (const int*)d_in[1];
    const int*   ea   = (const int*)d_in[2];
    const float* isoT = (const float*)d_in[4];
    const int*   ei2  = (const int*)d_in[5];
    const int*   asg  = (const int*)d_in[6];
    const float* embW = (const float*)d_in[8];
    const float* embB = (const float*)d_in[9];
    const float* gW1  = (const float*)d_in[10];
    const float* gb1  = (const float*)d_in[11];
    const float* gW2  = (const float*)d_in[12];
    const float* gb2  = (const float*)d_in[13];
    const float* ee1  = (const float*)d_in[14];
    const float* ee2  = (const float*)d_in[15];
    const float* bng  = (const float*)d_in[16];
    const float* bnb  = (const float*)d_in[17];
    const float* i1rW = (const float*)d_in[18];
    const float* i1rb = (const float*)d_in[19];
    const float* i1oW = (const float*)d_in[20];
    const float* i2rW = (const float*)d_in[21];
    const float* i2rb = (const float*)d_in[22];
    const float* i2oW = (const float*)d_in[23];
    const float* rW0  = (const float*)d_in[24];
    const float* rb0  = (const float*)d_in[25];
    const float* rW1  = (const float*)d_in[26];
    const float* rb1  = (const float*)d_in[27];
    const float* rW2  = (const float*)d_in[28];
    const float* rb2  = (const float*)d_in[29];
    const float* lW   = (const float*)d_in[30];
    const float* lb   = (const float*)d_in[31];
    float* out = (float*)d_out;

    const float* bngL = bng + (size_t)(NL - 1) * ND;
    const float* bnbL = bnb + (size_t)(NL - 1) * ND;

    // ---- fork ----
    cudaEventRecord(g_hx.evRoot, 0);
    cudaStreamWaitEvent(g_hx.sB, g_hx.evRoot, 0);
    k_embed<<<2048, 128, 0, g_hx.sB>>>(x, embW, embB);
    cudaEventRecord(g_hx.evB, g_hx.sB);
    cudaStreamWaitEvent(g_hx.sC, g_hx.evRoot, 0);
    k_zero2<<<128, 256, 0, g_hx.sC>>>();
    k_count2<<<NE2 / 256, 256, 0, g_hx.sC>>>(ei2);
    k_reserve2<<<NN2 / 256, 256, 0, g_hx.sC>>>();
    k_fill2<<<NE2 / 256, 256, 0, g_hx.sC>>>(ei2);
    k_iso<<<(NN2 + 255) / 256, 256, 0, g_hx.sC>>>(isoT);
    cudaEventRecord(g_hx.evC, g_hx.sC);

    // ---- graph-1 CSR build (main stream) ----
    k_zero1<<<256, 256>>>();
    k_count1<<<NE / 256, 256>>>(ei, ea);
    k_reserve1<<<NN / 256, 256>>>();
    k_fill1<<<NE / 256, 256>>>(ei);

    // ---- join embed before first aggregation ----
    cudaStreamWaitEvent(0, g_hx.evB, 0);

    // ---- GIN stack: BN+ReLU of layer l-1 folded into agg of layer l ----
    for (int l = 0; l < NL; l++) {
        k_agg1<<<NN / 8, 256>>>(ee1 + (size_t)l * 6 * ND, ee2 + (size_t)l * 3 * ND,
                                bng + (size_t)(l > 0 ? l - 1 : 0) * ND,
                                bnb + (size_t)(l > 0 ? l - 1 : 0) * ND, l);
        k_mlp<<<1280, 256>>>(gW1 + (size_t)l * ND * 128, gb1 + (size_t)l * 128,
                             gW2 + (size_t)l * 128 * ND, gb2 + (size_t)l * ND, l);
    }

    // ---- 2-set branch (join graph-2 CSR + iso first) ----
    cudaStreamWaitEvent(0, g_hx.evC, 0);
    k_proj<<<1184, 256>>>(i1rW, i1oW, asg, bngL, bnbL, 1);
    k_cagg<<<NN2 / 8, 256>>>(i1rb);
    k_proj<<<1184, 256>>>(i2rW, i2oW, asg, bngL, bnbL, 0);
    k_cagg<<<NN2 / 8, 256>>>(i2rb);

    // ---- fused pools + readout ----
    k_tail<<<NG, 256>>>(bngL, bnbL, rW0, rb0, rW1, rb1, rW2, rb2, lW, lb, out);
}